// round 2
// baseline (speedup 1.0000x reference)
#include <cuda_runtime.h>

#define NB 8
#define NC 512
#define NL 2048
#define NT 64

// Scratch (static device globals — no allocation in kernel_launch)
__device__ float g_Qt[NB * NT * NL];            // [b][t][l]  4 MB
__device__ float g_Kt[NB * NT * NL];            // [b][t][l]  4 MB
__device__ float g_S[(size_t)NB * NL * NL];     // [b][j][i]  128 MB
__device__ float g_m[NB * NL];
__device__ float g_rinv[NB * NL];

// ---------------------------------------------------------------------------
// Kernel 1: Q/K projection.  Qt[b][t][l] = sum_c W1[t][c] * x[b][c][l]
// Tile: 64 l per block, all 64 t, c in chunks of 32.
// ---------------------------------------------------------------------------
__global__ __launch_bounds__(256) void k_proj(const float* __restrict__ x,
                                              const float* __restrict__ W1,
                                              const float* __restrict__ W2) {
    __shared__ float xs[32][68];     // [c-chunk][l] pad 4 keeps float4 alignment
    __shared__ float w1s[64][33];
    __shared__ float w2s[64][33];
    const int b = blockIdx.y;
    const int l0 = blockIdx.x * 64;
    const int tid = threadIdx.x;
    const int tx = tid & 15, ty = tid >> 4;
    float qa[4][4] = {}, ka[4][4] = {};
    const float* xb = x + (size_t)b * NC * NL;

    for (int c0 = 0; c0 < NC; c0 += 32) {
#pragma unroll
        for (int u = 0; u < 8; u++) {
            int e = tid + u * 256;
            int cc = e >> 6, ll = e & 63;
            xs[cc][ll] = xb[(size_t)(c0 + cc) * NL + l0 + ll];
        }
#pragma unroll
        for (int u = 0; u < 8; u++) {
            int e = tid + u * 256;
            int t = e >> 5, cc = e & 31;
            w1s[t][cc] = W1[t * NC + c0 + cc];
            w2s[t][cc] = W2[t * NC + c0 + cc];
        }
        __syncthreads();
#pragma unroll
        for (int kc = 0; kc < 32; kc++) {
            float4 xv = *(const float4*)&xs[kc][tx * 4];
            float lv[4] = {xv.x, xv.y, xv.z, xv.w};
#pragma unroll
            for (int tt = 0; tt < 4; tt++) {
                float wq = w1s[ty * 4 + tt][kc];
                float wk = w2s[ty * 4 + tt][kc];
#pragma unroll
                for (int ll = 0; ll < 4; ll++) {
                    qa[tt][ll] += wq * lv[ll];
                    ka[tt][ll] += wk * lv[ll];
                }
            }
        }
        __syncthreads();
    }
#pragma unroll
    for (int tt = 0; tt < 4; tt++) {
        int t = ty * 4 + tt;
        float4 q4 = make_float4(qa[tt][0], qa[tt][1], qa[tt][2], qa[tt][3]);
        float4 k4 = make_float4(ka[tt][0], ka[tt][1], ka[tt][2], ka[tt][3]);
        *(float4*)&g_Qt[(size_t)(b * NT + t) * NL + l0 + tx * 4] = q4;
        *(float4*)&g_Kt[(size_t)(b * NT + t) * NL + l0 + tx * 4] = k4;
    }
}

// ---------------------------------------------------------------------------
// Kernel 2: scores.  S[b][j][i] = sum_t Qt[b][t][j] * Kt[b][t][i]
// 128x128 output tile, k (=t) chunks of 32, 8x8 microtile per thread.
// ---------------------------------------------------------------------------
__global__ __launch_bounds__(256) void k_scores() {
    __shared__ float Qs[32][132];
    __shared__ float Ks[32][132];
    const int b = blockIdx.z;
    const int j0 = blockIdx.y * 128;
    const int i0 = blockIdx.x * 128;
    const int tid = threadIdx.x;
    const int tx = tid & 15, ty = tid >> 4;
    float acc[8][8] = {};   // [j-sub][i-sub]
    const float* Qb = g_Qt + (size_t)b * NT * NL;
    const float* Kb = g_Kt + (size_t)b * NT * NL;

    for (int t0 = 0; t0 < NT; t0 += 32) {
#pragma unroll
        for (int u = 0; u < 16; u++) {
            int e = tid + u * 256;
            int t = e >> 7, j = e & 127;
            Qs[t][j] = Qb[(size_t)(t0 + t) * NL + j0 + j];
            Ks[t][j] = Kb[(size_t)(t0 + t) * NL + i0 + j];
        }
        __syncthreads();
#pragma unroll
        for (int kc = 0; kc < 32; kc++) {
            float4 qa4 = *(const float4*)&Qs[kc][ty * 4];
            float4 qb4 = *(const float4*)&Qs[kc][ty * 4 + 64];
            float4 ka4 = *(const float4*)&Ks[kc][tx * 4];
            float4 kb4 = *(const float4*)&Ks[kc][tx * 4 + 64];
            float jv[8] = {qa4.x, qa4.y, qa4.z, qa4.w, qb4.x, qb4.y, qb4.z, qb4.w};
            float iv[8] = {ka4.x, ka4.y, ka4.z, ka4.w, kb4.x, kb4.y, kb4.z, kb4.w};
#pragma unroll
            for (int jj = 0; jj < 8; jj++)
#pragma unroll
                for (int ii = 0; ii < 8; ii++)
                    acc[jj][ii] += jv[jj] * iv[ii];
        }
        __syncthreads();
    }
    float* Sb = g_S + (size_t)b * NL * NL;
#pragma unroll
    for (int jj = 0; jj < 8; jj++) {
        int j = j0 + ty * 4 + (jj & 3) + ((jj >> 2) << 6);
        float4 s0 = make_float4(acc[jj][0], acc[jj][1], acc[jj][2], acc[jj][3]);
        float4 s1 = make_float4(acc[jj][4], acc[jj][5], acc[jj][6], acc[jj][7]);
        *(float4*)&Sb[(size_t)j * NL + i0 + tx * 4] = s0;
        *(float4*)&Sb[(size_t)j * NL + i0 + tx * 4 + 64] = s1;
    }
}

// ---------------------------------------------------------------------------
// Kernel 3: per-row max + 1/sum(exp).  One warp per row.
// ---------------------------------------------------------------------------
__global__ __launch_bounds__(256) void k_stats() {
    const int row = blockIdx.x * 8 + (threadIdx.x >> 5);   // [0, NB*NL)
    const int lane = threadIdx.x & 31;
    const float* Srow = g_S + (size_t)row * NL;
    float m = -1e30f;
    for (int i = lane; i < NL; i += 32) m = fmaxf(m, Srow[i]);
#pragma unroll
    for (int o = 16; o; o >>= 1) m = fmaxf(m, __shfl_xor_sync(0xffffffffu, m, o));
    float s = 0.f;
    for (int i = lane; i < NL; i += 32) s += __expf(Srow[i] - m);
#pragma unroll
    for (int o = 16; o; o >>= 1) s += __shfl_xor_sync(0xffffffffu, s, o);
    if (lane == 0) { g_m[row] = m; g_rinv[row] = 1.0f / s; }
}

// ---------------------------------------------------------------------------
// Kernel 4: out[b][c][j] = x[b][c][j] + g * (1/sum_j) * sum_i exp(S[j][i]-m_j) * x[b][c][i]
// 128(c) x 128(j) tile, i chunks of 32, 8x8 microtile. Dominant kernel.
// ---------------------------------------------------------------------------
__global__ __launch_bounds__(256) void k_out(const float* __restrict__ x,
                                             const float* __restrict__ gam,
                                             float* __restrict__ out) {
    __shared__ float ps[32][132];   // [i][j]  exp(S - m)
    __shared__ float vs[32][132];   // [i][c]  x values
    const int b = blockIdx.z;
    const int j0 = blockIdx.x * 128;
    const int c0 = blockIdx.y * 128;
    const int tid = threadIdx.x;
    const int tx = tid & 15, ty = tid >> 4;
    float acc[8][8] = {};   // [c-sub][j-sub]
    const float* Sb = g_S + (size_t)b * NL * NL;
    const float* xb = x + (size_t)b * NC * NL;
    const float* mb = g_m + b * NL;

    for (int i0 = 0; i0 < NL; i0 += 32) {
#pragma unroll
        for (int u = 0; u < 16; u++) {
            int e = tid + u * 256;
            int r = e >> 5, i = e & 31;     // r indexes j (for ps) and c (for vs)
            float s = Sb[(size_t)(j0 + r) * NL + i0 + i];
            ps[i][r] = __expf(s - mb[j0 + r]);
            vs[i][r] = xb[(size_t)(c0 + r) * NL + i0 + i];
        }
        __syncthreads();
#pragma unroll
        for (int kc = 0; kc < 32; kc++) {
            float4 pa = *(const float4*)&ps[kc][tx * 4];
            float4 pb = *(const float4*)&ps[kc][tx * 4 + 64];
            float4 va = *(const float4*)&vs[kc][ty * 4];
            float4 vb = *(const float4*)&vs[kc][ty * 4 + 64];
            float pv[8] = {pa.x, pa.y, pa.z, pa.w, pb.x, pb.y, pb.z, pb.w};
            float vv[8] = {va.x, va.y, va.z, va.w, vb.x, vb.y, vb.z, vb.w};
#pragma unroll
            for (int cc = 0; cc < 8; cc++)
#pragma unroll
                for (int jj = 0; jj < 8; jj++)
                    acc[cc][jj] += vv[cc] * pv[jj];
        }
        __syncthreads();
    }

    const float g = *gam;
    float rv[8];
#pragma unroll
    for (int jj = 0; jj < 8; jj++)
        rv[jj] = g_rinv[b * NL + j0 + tx * 4 + (jj & 3) + ((jj >> 2) << 6)];

#pragma unroll
    for (int cc = 0; cc < 8; cc++) {
        int c = c0 + ty * 4 + (cc & 3) + ((cc >> 2) << 6);
        size_t xrow = (size_t)c * NL + j0 + tx * 4;
        size_t orow = (size_t)(b * NC + c) * NL + j0 + tx * 4;
        float4 x0 = *(const float4*)&xb[xrow];
        float4 x1 = *(const float4*)&xb[xrow + 64];
        float4 o0, o1;
        o0.x = x0.x + g * acc[cc][0] * rv[0];
        o0.y = x0.y + g * acc[cc][1] * rv[1];
        o0.z = x0.z + g * acc[cc][2] * rv[2];
        o0.w = x0.w + g * acc[cc][3] * rv[3];
        o1.x = x1.x + g * acc[cc][4] * rv[4];
        o1.y = x1.y + g * acc[cc][5] * rv[5];
        o1.z = x1.z + g * acc[cc][6] * rv[6];
        o1.w = x1.w + g * acc[cc][7] * rv[7];
        *(float4*)&out[orow] = o0;
        *(float4*)&out[orow + 64] = o1;
    }
}

// ---------------------------------------------------------------------------
extern "C" void kernel_launch(void* const* d_in, const int* in_sizes, int n_in,
                              void* d_out, int out_size) {
    (void)in_sizes; (void)n_in; (void)out_size;
    const float* x   = (const float*)d_in[0];
    const float* W1  = (const float*)d_in[1];
    const float* W2  = (const float*)d_in[2];
    const float* gam = (const float*)d_in[3];
    float* out = (float*)d_out;

    k_proj  <<<dim3(NL / 64, NB), 256>>>(x, W1, W2);
    k_scores<<<dim3(NL / 128, NL / 128, NB), 256>>>();
    k_stats <<<NB * NL / 8, 256>>>();
    k_out   <<<dim3(NL / 128, NC / 128, NB), 256>>>(x, gam, out);
}

// round 4
// speedup vs baseline: 2.4127x; 2.4127x over previous
#include <cuda_runtime.h>
#include <cstdint>

#define NB 8
#define NC 512
#define NL 2048
#define NT 64

// Scratch (static device globals — no allocation in kernel_launch)
__device__ float g_Qt[NB * NT * NL];            // [b][t][l]  4 MB
__device__ float g_Kt[NB * NT * NL];            // [b][t][l]  4 MB
__device__ float g_S[(size_t)NB * NL * NL];     // [b][j][i]  scores -> P (tf32)  128 MB
__device__ float g_Xr[(size_t)NB * NC * NL];    // x rounded to tf32             64 MB

__device__ __forceinline__ float to_tf32(float v) {
    uint32_t r;
    asm("cvt.rna.tf32.f32 %0, %1;" : "=r"(r) : "f"(v));
    return __uint_as_float(r);
}
__device__ __forceinline__ uint32_t smem_u32(const void* p) {
    uint32_t r;
    asm("{ .reg .u64 t; cvta.to.shared.u64 t, %1; cvt.u32.u64 %0, t; }" : "=r"(r) : "l"(p));
    return r;
}
__device__ __forceinline__ void cp16(uint32_t dst, const void* src) {
    asm volatile("cp.async.cg.shared.global [%0], [%1], 16;\n" :: "r"(dst), "l"(src));
}

// ---------------------------------------------------------------------------
// Kernel 1: Q/K projection.  Qt[b][t][l] = sum_c W1[t][c] * x[b][c][l]
// ---------------------------------------------------------------------------
__global__ __launch_bounds__(256) void k_proj(const float* __restrict__ x,
                                              const float* __restrict__ W1,
                                              const float* __restrict__ W2) {
    __shared__ float xs[32][68];
    __shared__ float w1s[64][33];
    __shared__ float w2s[64][33];
    const int b = blockIdx.y;
    const int l0 = blockIdx.x * 64;
    const int tid = threadIdx.x;
    const int tx = tid & 15, ty = tid >> 4;
    float qa[4][4] = {}, ka[4][4] = {};
    const float* xb = x + (size_t)b * NC * NL;

    for (int c0 = 0; c0 < NC; c0 += 32) {
#pragma unroll
        for (int u = 0; u < 8; u++) {
            int e = tid + u * 256;
            int cc = e >> 6, ll = e & 63;
            xs[cc][ll] = xb[(size_t)(c0 + cc) * NL + l0 + ll];
        }
#pragma unroll
        for (int u = 0; u < 8; u++) {
            int e = tid + u * 256;
            int t = e >> 5, cc = e & 31;
            w1s[t][cc] = W1[t * NC + c0 + cc];
            w2s[t][cc] = W2[t * NC + c0 + cc];
        }
        __syncthreads();
#pragma unroll
        for (int kc = 0; kc < 32; kc++) {
            float4 xv = *(const float4*)&xs[kc][tx * 4];
            float lv[4] = {xv.x, xv.y, xv.z, xv.w};
#pragma unroll
            for (int tt = 0; tt < 4; tt++) {
                float wq = w1s[ty * 4 + tt][kc];
                float wk = w2s[ty * 4 + tt][kc];
#pragma unroll
                for (int ll = 0; ll < 4; ll++) {
                    qa[tt][ll] += wq * lv[ll];
                    ka[tt][ll] += wk * lv[ll];
                }
            }
        }
        __syncthreads();
    }
#pragma unroll
    for (int tt = 0; tt < 4; tt++) {
        int t = ty * 4 + tt;
        float4 q4 = make_float4(qa[tt][0], qa[tt][1], qa[tt][2], qa[tt][3]);
        float4 k4 = make_float4(ka[tt][0], ka[tt][1], ka[tt][2], ka[tt][3]);
        *(float4*)&g_Qt[(size_t)(b * NT + t) * NL + l0 + tx * 4] = q4;
        *(float4*)&g_Kt[(size_t)(b * NT + t) * NL + l0 + tx * 4] = k4;
    }
}

// ---------------------------------------------------------------------------
// Kernel 2: scores.  S[b][j][i] = sum_t Qt[b][t][j] * Kt[b][t][i]
// ---------------------------------------------------------------------------
__global__ __launch_bounds__(256) void k_scores() {
    __shared__ float Qs[32][132];
    __shared__ float Ks[32][132];
    const int b = blockIdx.z;
    const int j0 = blockIdx.y * 128;
    const int i0 = blockIdx.x * 128;
    const int tid = threadIdx.x;
    const int tx = tid & 15, ty = tid >> 4;
    float acc[8][8] = {};
    const float* Qb = g_Qt + (size_t)b * NT * NL;
    const float* Kb = g_Kt + (size_t)b * NT * NL;

    for (int t0 = 0; t0 < NT; t0 += 32) {
#pragma unroll
        for (int u = 0; u < 16; u++) {
            int e = tid + u * 256;
            int t = e >> 7, j = e & 127;
            Qs[t][j] = Qb[(size_t)(t0 + t) * NL + j0 + j];
            Ks[t][j] = Kb[(size_t)(t0 + t) * NL + i0 + j];
        }
        __syncthreads();
#pragma unroll
        for (int kc = 0; kc < 32; kc++) {
            float4 qa4 = *(const float4*)&Qs[kc][ty * 4];
            float4 qb4 = *(const float4*)&Qs[kc][ty * 4 + 64];
            float4 ka4 = *(const float4*)&Ks[kc][tx * 4];
            float4 kb4 = *(const float4*)&Ks[kc][tx * 4 + 64];
            float jv[8] = {qa4.x, qa4.y, qa4.z, qa4.w, qb4.x, qb4.y, qb4.z, qb4.w};
            float iv[8] = {ka4.x, ka4.y, ka4.z, ka4.w, kb4.x, kb4.y, kb4.z, kb4.w};
#pragma unroll
            for (int jj = 0; jj < 8; jj++)
#pragma unroll
                for (int ii = 0; ii < 8; ii++)
                    acc[jj][ii] += jv[jj] * iv[ii];
        }
        __syncthreads();
    }
    float* Sb = g_S + (size_t)b * NL * NL;
#pragma unroll
    for (int jj = 0; jj < 8; jj++) {
        int j = j0 + ty * 4 + (jj & 3) + ((jj >> 2) << 6);
        float4 s0 = make_float4(acc[jj][0], acc[jj][1], acc[jj][2], acc[jj][3]);
        float4 s1 = make_float4(acc[jj][4], acc[jj][5], acc[jj][6], acc[jj][7]);
        *(float4*)&Sb[(size_t)j * NL + i0 + tx * 4] = s0;
        *(float4*)&Sb[(size_t)j * NL + i0 + tx * 4 + 64] = s1;
    }
}

// ---------------------------------------------------------------------------
// Kernel 3: softmax rows in-place.  g_S row -> tf32(exp(s-m)/sum), one pass.
// One warp per row, full row in 64 regs.
// ---------------------------------------------------------------------------
__global__ __launch_bounds__(256) void k_stats() {
    const int row = blockIdx.x * 8 + (threadIdx.x >> 5);
    const int lane = threadIdx.x & 31;
    float* Srow = g_S + (size_t)row * NL;
    float v[64];
#pragma unroll
    for (int u = 0; u < 64; u++) v[u] = Srow[u * 32 + lane];
    float m = -1e30f;
#pragma unroll
    for (int u = 0; u < 64; u++) m = fmaxf(m, v[u]);
#pragma unroll
    for (int o = 16; o; o >>= 1) m = fmaxf(m, __shfl_xor_sync(0xffffffffu, m, o));
    float s = 0.f;
#pragma unroll
    for (int u = 0; u < 64; u++) { v[u] = __expf(v[u] - m); s += v[u]; }
#pragma unroll
    for (int o = 16; o; o >>= 1) s += __shfl_xor_sync(0xffffffffu, s, o);
    const float rinv = 1.0f / s;
#pragma unroll
    for (int u = 0; u < 64; u++) Srow[u * 32 + lane] = to_tf32(v[u] * rinv);
}

// ---------------------------------------------------------------------------
// Kernel 3b: round x to tf32 once (unbiased rna) into g_Xr.
// ---------------------------------------------------------------------------
__global__ __launch_bounds__(256) void k_round(const float* __restrict__ x) {
    const size_t e = ((size_t)blockIdx.x * 256 + threadIdx.x) * 4;
    float4 v = *(const float4*)(x + e);
    v.x = to_tf32(v.x); v.y = to_tf32(v.y); v.z = to_tf32(v.z); v.w = to_tf32(v.w);
    *(float4*)(g_Xr + e) = v;
}

// ---------------------------------------------------------------------------
// Kernel 4 (mma.sync tf32): out[b][c][j] = x[b][c][j] + g * sum_i P[j][i]*xr[b][c][i]
// CTA: 128(c) x 128(j), 8 warps (4m x 2n), warp tile 32x64, K chunks of 32.
// cp.async double buffer; smem rows padded to 36 floats (conflict-free frags).
// ---------------------------------------------------------------------------
#define ICH 32
#define NCHK (NL / ICH)            // 64
#define ROWP 36
#define TILE_F (128 * ROWP)        // floats per tile
#define STG_F (2 * TILE_F)         // xs + ps per stage
#define SMEM_OUT (2 * STG_F * 4)   // bytes = 73728

#define MMA_TF32(ac, A, b0v, b1v)                                             \
    asm volatile("mma.sync.aligned.m16n8k8.row.col.f32.tf32.tf32.f32 "        \
                 "{%0,%1,%2,%3}, {%4,%5,%6,%7}, {%8,%9}, {%0,%1,%2,%3};"      \
                 : "+f"(ac[0]), "+f"(ac[1]), "+f"(ac[2]), "+f"(ac[3])         \
                 : "r"(A[0]), "r"(A[1]), "r"(A[2]), "r"(A[3]),                \
                   "r"(b0v), "r"(b1v));

__global__ __launch_bounds__(256, 2) void k_out_mma(const float* __restrict__ x,
                                                    const float* __restrict__ gam,
                                                    float* __restrict__ out) {
    extern __shared__ float sm[];
    const uint32_t sb = smem_u32(sm);
    const int tid = threadIdx.x;
    const int b = blockIdx.z;
    const int c0 = blockIdx.y * 128;
    const int j0 = blockIdx.x * 128;
    const float* xrb = g_Xr + (size_t)b * NC * NL;
    const float* Pb = g_S + (size_t)b * NL * NL;

    // ---- async chunk loader: xs rows = xr[c0+r][i0+..], ps rows = P[j0+r][i0+..]
    auto load_chunk = [&](int n, int stg) {
        const int i0 = n * ICH;
        const uint32_t xbase = sb + (uint32_t)(stg * STG_F) * 4;
        const uint32_t pbase = xbase + TILE_F * 4;
#pragma unroll
        for (int u = 0; u < 4; u++) {
            int e = tid + u * 256;
            int r = e >> 3, seg = e & 7;
            cp16(xbase + (r * ROWP + seg * 4) * 4, xrb + (size_t)(c0 + r) * NL + i0 + seg * 4);
        }
#pragma unroll
        for (int u = 0; u < 4; u++) {
            int e = tid + u * 256;
            int r = e >> 3, seg = e & 7;
            cp16(pbase + (r * ROWP + seg * 4) * 4, Pb + (size_t)(j0 + r) * NL + i0 + seg * 4);
        }
        asm volatile("cp.async.commit_group;\n" ::: "memory");
    };

    const int wid = tid >> 5, lane = tid & 31;
    const int wm = wid & 3;        // c block: wm*32
    const int wn = wid >> 2;       // j block: wn*64
    const int grp = lane >> 2, qid = lane & 3;

    float acc[2][8][4];
#pragma unroll
    for (int mt = 0; mt < 2; mt++)
#pragma unroll
        for (int nt = 0; nt < 8; nt++)
#pragma unroll
            for (int q = 0; q < 4; q++) acc[mt][nt][q] = 0.f;

    load_chunk(0, 0);

    for (int n = 0; n < NCHK; n++) {
        const int s = n & 1;
        if (n + 1 < NCHK) {
            load_chunk(n + 1, 1 - s);
            asm volatile("cp.async.wait_group 1;\n" ::: "memory");
        } else {
            asm volatile("cp.async.wait_group 0;\n" ::: "memory");
        }
        __syncthreads();

        const float* xs = sm + s * STG_F;
        const float* ps = xs + TILE_F;
#pragma unroll
        for (int ks = 0; ks < 4; ks++) {
            const int k = ks * 8;
            uint32_t a[2][4];
#pragma unroll
            for (int mt = 0; mt < 2; mt++) {
                const float* r0 = &xs[(wm * 32 + mt * 16 + grp) * ROWP + k + qid];
                const float* r8 = r0 + 8 * ROWP;
                a[mt][0] = __float_as_uint(r0[0]);
                a[mt][1] = __float_as_uint(r8[0]);
                a[mt][2] = __float_as_uint(r0[4]);
                a[mt][3] = __float_as_uint(r8[4]);
            }
#pragma unroll
            for (int nt = 0; nt < 8; nt++) {
                const float* pr = &ps[(wn * 64 + nt * 8 + grp) * ROWP + k + qid];
                uint32_t b0 = __float_as_uint(pr[0]);
                uint32_t b1 = __float_as_uint(pr[4]);
                MMA_TF32(acc[0][nt], a[0], b0, b1);
                MMA_TF32(acc[1][nt], a[1], b0, b1);
            }
        }
        __syncthreads();
    }

    // ---- epilogue: out = x + g * acc   (rinv already folded into P)
    const float g = *gam;
    const float* xb = x + (size_t)b * NC * NL;
    float* ob = out + (size_t)b * NC * NL;
#pragma unroll
    for (int mt = 0; mt < 2; mt++) {
        const int c = c0 + wm * 32 + mt * 16 + grp;
#pragma unroll
        for (int nt = 0; nt < 8; nt++) {
            const int j = j0 + wn * 64 + nt * 8 + qid * 2;
            {
                const size_t o = (size_t)c * NL + j;
                float2 xv = *(const float2*)(xb + o);
                float2 r = make_float2(xv.x + g * acc[mt][nt][0],
                                       xv.y + g * acc[mt][nt][1]);
                *(float2*)(ob + o) = r;
            }
            {
                const size_t o = (size_t)(c + 8) * NL + j;
                float2 xv = *(const float2*)(xb + o);
                float2 r = make_float2(xv.x + g * acc[mt][nt][2],
                                       xv.y + g * acc[mt][nt][3]);
                *(float2*)(ob + o) = r;
            }
        }
    }
}

// ---------------------------------------------------------------------------
extern "C" void kernel_launch(void* const* d_in, const int* in_sizes, int n_in,
                              void* d_out, int out_size) {
    (void)in_sizes; (void)n_in; (void)out_size;
    const float* x   = (const float*)d_in[0];
    const float* W1  = (const float*)d_in[1];
    const float* W2  = (const float*)d_in[2];
    const float* gam = (const float*)d_in[3];
    float* out = (float*)d_out;

    cudaFuncSetAttribute(k_out_mma, cudaFuncAttributeMaxDynamicSharedMemorySize, SMEM_OUT);

    k_proj   <<<dim3(NL / 64, NB), 256>>>(x, W1, W2);
    k_scores <<<dim3(NL / 128, NL / 128, NB), 256>>>();
    k_stats  <<<NB * NL / 8, 256>>>();
    k_round  <<<(NB * NC * NL) / 1024, 256>>>(x);
    k_out_mma<<<dim3(NL / 128, NC / 128, NB), 256, SMEM_OUT>>>(x, gam, out);
}

// round 5
// speedup vs baseline: 2.7896x; 1.1562x over previous
#include <cuda_runtime.h>
#include <cstdint>

#define NB 8
#define NC 512
#define NL 2048
#define NT 64

// Scratch (static device globals — no allocation in kernel_launch)
__device__ float g_Q[NB * NL * NT];             // [b][l][t]  4 MB (fp32)
__device__ float g_K[NB * NL * NT];             // [b][l][t]  4 MB (fp32)
__device__ float g_S[(size_t)NB * NL * NL];     // [b][j][i]  unnormalized P (tf32)  128 MB
__device__ float g_Xr[(size_t)NB * NC * NL];    // x rounded to tf32                 64 MB
__device__ float g_sum[NB * NL];
__device__ float g_rinv[NB * NL];

__device__ __forceinline__ float to_tf32(float v) {
    uint32_t r;
    asm("cvt.rna.tf32.f32 %0, %1;" : "=r"(r) : "f"(v));
    return __uint_as_float(r);
}
__device__ __forceinline__ uint32_t smem_u32(const void* p) {
    uint32_t r;
    asm("{ .reg .u64 t; cvta.to.shared.u64 t, %1; cvt.u32.u64 %0, t; }" : "=r"(r) : "l"(p));
    return r;
}
__device__ __forceinline__ void cp16(uint32_t dst, const void* src) {
    asm volatile("cp.async.cg.shared.global [%0], [%1], 16;\n" :: "r"(dst), "l"(src));
}

#define MMA_TF32(ac, A, b0v, b1v)                                             \
    asm volatile("mma.sync.aligned.m16n8k8.row.col.f32.tf32.tf32.f32 "        \
                 "{%0,%1,%2,%3}, {%4,%5,%6,%7}, {%8,%9}, {%0,%1,%2,%3};"      \
                 : "+f"(ac[0]), "+f"(ac[1]), "+f"(ac[2]), "+f"(ac[3])         \
                 : "r"(A[0]), "r"(A[1]), "r"(A[2]), "r"(A[3]),                \
                   "r"(b0v), "r"(b1v));

// ---------------------------------------------------------------------------
// Tiny kernels: zero g_sum; invert sums.
// ---------------------------------------------------------------------------
__global__ void k_zero() { g_sum[blockIdx.x * 1024 + threadIdx.x] = 0.f; }
__global__ void k_rinv() {
    const int i = blockIdx.x * 1024 + threadIdx.x;
    g_rinv[i] = 1.0f / g_sum[i];
}

// ---------------------------------------------------------------------------
// Kernel 1: Q/K projection -> [b][l][t] layout (t contiguous).
// ---------------------------------------------------------------------------
__global__ __launch_bounds__(256) void k_proj(const float* __restrict__ x,
                                              const float* __restrict__ W1,
                                              const float* __restrict__ W2) {
    __shared__ float xs[32][68];
    __shared__ float w1s[64][33];
    __shared__ float w2s[64][33];
    const int b = blockIdx.y;
    const int l0 = blockIdx.x * 64;
    const int tid = threadIdx.x;
    const int tx = tid & 15, ty = tid >> 4;
    float qa[4][4] = {}, ka[4][4] = {};
    const float* xb = x + (size_t)b * NC * NL;

    for (int c0 = 0; c0 < NC; c0 += 32) {
#pragma unroll
        for (int u = 0; u < 8; u++) {
            int e = tid + u * 256;
            int cc = e >> 6, ll = e & 63;
            xs[cc][ll] = xb[(size_t)(c0 + cc) * NL + l0 + ll];
        }
#pragma unroll
        for (int u = 0; u < 8; u++) {
            int e = tid + u * 256;
            int t = e >> 5, cc = e & 31;
            w1s[t][cc] = W1[t * NC + c0 + cc];
            w2s[t][cc] = W2[t * NC + c0 + cc];
        }
        __syncthreads();
#pragma unroll
        for (int kc = 0; kc < 32; kc++) {
            float4 xv = *(const float4*)&xs[kc][tx * 4];
            float lv[4] = {xv.x, xv.y, xv.z, xv.w};
#pragma unroll
            for (int tt = 0; tt < 4; tt++) {
                float wq = w1s[ty * 4 + tt][kc];
                float wk = w2s[ty * 4 + tt][kc];
#pragma unroll
                for (int ll = 0; ll < 4; ll++) {
                    qa[tt][ll] += wq * lv[ll];
                    ka[tt][ll] += wk * lv[ll];
                }
            }
        }
        __syncthreads();
    }
#pragma unroll
    for (int ll = 0; ll < 4; ll++) {
        const int l = l0 + tx * 4 + ll;
        float4 q4 = make_float4(qa[0][ll], qa[1][ll], qa[2][ll], qa[3][ll]);
        float4 k4 = make_float4(ka[0][ll], ka[1][ll], ka[2][ll], ka[3][ll]);
        *(float4*)&g_Q[((size_t)b * NL + l) * NT + ty * 4] = q4;
        *(float4*)&g_K[((size_t)b * NL + l) * NT + ty * 4] = k4;
    }
}

// ---------------------------------------------------------------------------
// Kernel 2 (mma tf32, hi/lo split): P[b][j][i] = tf32(exp(Q[j]·K[i])), and
// row sums into g_sum via atomics. No max subtraction (scores bounded ~±50).
// CTA 128j x 128i, warps 4(j) x 2(i), warp tile 32x64, K=64 single tile.
// ---------------------------------------------------------------------------
#define SROWP 68
#define STILE_F (128 * SROWP)
#define SMEM_SC (2 * STILE_F * 4)   // 69632 B

__global__ __launch_bounds__(256) void k_scores_mma() {
    extern __shared__ float sm[];
    const uint32_t sb = smem_u32(sm);
    const int tid = threadIdx.x;
    const int b = blockIdx.z;
    const int j0 = blockIdx.y * 128;
    const int i0 = blockIdx.x * 128;
    const float* Qb = g_Q + (size_t)b * NL * NT;
    const float* Kb = g_K + (size_t)b * NL * NT;

    // load Q tile [128][64] and K tile [128][64] (rows padded to 68)
#pragma unroll
    for (int u = 0; u < 8; u++) {
        int e = tid + u * 256;
        int r = e >> 4, seg = e & 15;
        cp16(sb + (r * SROWP + seg * 4) * 4, Qb + (size_t)(j0 + r) * NT + seg * 4);
        cp16(sb + (STILE_F + r * SROWP + seg * 4) * 4, Kb + (size_t)(i0 + r) * NT + seg * 4);
    }
    asm volatile("cp.async.commit_group;\n" ::: "memory");
    asm volatile("cp.async.wait_group 0;\n" ::: "memory");
    __syncthreads();

    const float* qs = sm;
    const float* ks = sm + STILE_F;
    const int wid = tid >> 5, lane = tid & 31;
    const int wm = wid & 3;            // j block: wm*32
    const int wn = wid >> 2;           // i block: wn*64
    const int grp = lane >> 2, qid = lane & 3;

    float acc[2][8][4];
#pragma unroll
    for (int mt = 0; mt < 2; mt++)
#pragma unroll
        for (int nt = 0; nt < 8; nt++)
#pragma unroll
            for (int q = 0; q < 4; q++) acc[mt][nt][q] = 0.f;

#pragma unroll
    for (int ks8 = 0; ks8 < 8; ks8++) {
        const int k = ks8 * 8;
        uint32_t ahi[2][4], alo[2][4];
#pragma unroll
        for (int mt = 0; mt < 2; mt++) {
            const float* r0 = &qs[(wm * 32 + mt * 16 + grp) * SROWP + k + qid];
            const float* r8 = r0 + 8 * SROWP;
            float v[4] = {r0[0], r8[0], r0[4], r8[4]};
#pragma unroll
            for (int q = 0; q < 4; q++) {
                float hi = to_tf32(v[q]);
                ahi[mt][q] = __float_as_uint(hi);
                alo[mt][q] = __float_as_uint(to_tf32(v[q] - hi));
            }
        }
        uint32_t bhi[8][2], blo[8][2];
#pragma unroll
        for (int nt = 0; nt < 8; nt++) {
            const float* pr = &ks[(wn * 64 + nt * 8 + grp) * SROWP + k + qid];
            float v0 = pr[0], v1 = pr[4];
            float h0 = to_tf32(v0), h1 = to_tf32(v1);
            bhi[nt][0] = __float_as_uint(h0);
            bhi[nt][1] = __float_as_uint(h1);
            blo[nt][0] = __float_as_uint(to_tf32(v0 - h0));
            blo[nt][1] = __float_as_uint(to_tf32(v1 - h1));
        }
#pragma unroll
        for (int nt = 0; nt < 8; nt++)
#pragma unroll
            for (int mt = 0; mt < 2; mt++) {
                MMA_TF32(acc[mt][nt], ahi[mt], bhi[nt][0], bhi[nt][1]);
                MMA_TF32(acc[mt][nt], ahi[mt], blo[nt][0], blo[nt][1]);
                MMA_TF32(acc[mt][nt], alo[mt], bhi[nt][0], bhi[nt][1]);
            }
    }

    // epilogue: P = tf32(exp(s)) (unnormalized), store; row sums -> atomicAdd
    float* Pb = g_S + (size_t)b * NL * NL;
    float rsum[2][2] = {};
#pragma unroll
    for (int mt = 0; mt < 2; mt++) {
        const int r0 = j0 + wm * 32 + mt * 16 + grp;
#pragma unroll
        for (int nt = 0; nt < 8; nt++) {
            const int col = i0 + wn * 64 + nt * 8 + qid * 2;
            float e0 = to_tf32(__expf(acc[mt][nt][0]));
            float e1 = to_tf32(__expf(acc[mt][nt][1]));
            float e2 = to_tf32(__expf(acc[mt][nt][2]));
            float e3 = to_tf32(__expf(acc[mt][nt][3]));
            rsum[mt][0] += e0 + e1;
            rsum[mt][1] += e2 + e3;
            *(float2*)&Pb[(size_t)r0 * NL + col] = make_float2(e0, e1);
            *(float2*)&Pb[(size_t)(r0 + 8) * NL + col] = make_float2(e2, e3);
        }
    }
#pragma unroll
    for (int mt = 0; mt < 2; mt++)
#pragma unroll
        for (int h = 0; h < 2; h++) {
            float v = rsum[mt][h];
            v += __shfl_xor_sync(0xffffffffu, v, 1);
            v += __shfl_xor_sync(0xffffffffu, v, 2);
            if (qid == 0)
                atomicAdd(&g_sum[b * NL + j0 + wm * 32 + mt * 16 + grp + h * 8], v);
        }
}

// ---------------------------------------------------------------------------
// Kernel 3b: round x to tf32 once (unbiased rna) into g_Xr.
// ---------------------------------------------------------------------------
__global__ __launch_bounds__(256) void k_round(const float* __restrict__ x) {
    const size_t e = ((size_t)blockIdx.x * 256 + threadIdx.x) * 4;
    float4 v = *(const float4*)(x + e);
    v.x = to_tf32(v.x); v.y = to_tf32(v.y); v.z = to_tf32(v.z); v.w = to_tf32(v.w);
    *(float4*)(g_Xr + e) = v;
}

// ---------------------------------------------------------------------------
// Kernel 4 (mma tf32): out[b][c][j] = x[b][c][j] + g*rinv_j*sum_i P[j][i]*xr[b][c][i]
// CTA: 128(c) x 128(j), 8 warps (4m x 2n), warp tile 32x64, K chunks of 32.
// ---------------------------------------------------------------------------
#define ICH 32
#define NCHK (NL / ICH)            // 64
#define ROWP 36
#define TILE_F (128 * ROWP)
#define STG_F (2 * TILE_F)
#define SMEM_OUT (2 * STG_F * 4)   // 73728 B

__global__ __launch_bounds__(256, 2) void k_out_mma(const float* __restrict__ x,
                                                    const float* __restrict__ gam,
                                                    float* __restrict__ out) {
    extern __shared__ float sm[];
    const uint32_t sb = smem_u32(sm);
    const int tid = threadIdx.x;
    const int b = blockIdx.z;
    const int c0 = blockIdx.y * 128;
    const int j0 = blockIdx.x * 128;
    const float* xrb = g_Xr + (size_t)b * NC * NL;
    const float* Pb = g_S + (size_t)b * NL * NL;

    auto load_chunk = [&](int n, int stg) {
        const int i0 = n * ICH;
        const uint32_t xbase = sb + (uint32_t)(stg * STG_F) * 4;
        const uint32_t pbase = xbase + TILE_F * 4;
#pragma unroll
        for (int u = 0; u < 4; u++) {
            int e = tid + u * 256;
            int r = e >> 3, seg = e & 7;
            cp16(xbase + (r * ROWP + seg * 4) * 4, xrb + (size_t)(c0 + r) * NL + i0 + seg * 4);
        }
#pragma unroll
        for (int u = 0; u < 4; u++) {
            int e = tid + u * 256;
            int r = e >> 3, seg = e & 7;
            cp16(pbase + (r * ROWP + seg * 4) * 4, Pb + (size_t)(j0 + r) * NL + i0 + seg * 4);
        }
        asm volatile("cp.async.commit_group;\n" ::: "memory");
    };

    const int wid = tid >> 5, lane = tid & 31;
    const int wm = wid & 3;        // c block
    const int wn = wid >> 2;       // j block
    const int grp = lane >> 2, qid = lane & 3;

    float acc[2][8][4];
#pragma unroll
    for (int mt = 0; mt < 2; mt++)
#pragma unroll
        for (int nt = 0; nt < 8; nt++)
#pragma unroll
            for (int q = 0; q < 4; q++) acc[mt][nt][q] = 0.f;

    load_chunk(0, 0);

    for (int n = 0; n < NCHK; n++) {
        const int s = n & 1;
        if (n + 1 < NCHK) {
            load_chunk(n + 1, 1 - s);
            asm volatile("cp.async.wait_group 1;\n" ::: "memory");
        } else {
            asm volatile("cp.async.wait_group 0;\n" ::: "memory");
        }
        __syncthreads();

        const float* xs = sm + s * STG_F;
        const float* ps = xs + TILE_F;
#pragma unroll
        for (int ks8 = 0; ks8 < 4; ks8++) {
            const int k = ks8 * 8;
            uint32_t a[2][4];
#pragma unroll
            for (int mt = 0; mt < 2; mt++) {
                const float* r0 = &xs[(wm * 32 + mt * 16 + grp) * ROWP + k + qid];
                const float* r8 = r0 + 8 * ROWP;
                a[mt][0] = __float_as_uint(r0[0]);
                a[mt][1] = __float_as_uint(r8[0]);
                a[mt][2] = __float_as_uint(r0[4]);
                a[mt][3] = __float_as_uint(r8[4]);
            }
#pragma unroll
            for (int nt = 0; nt < 8; nt++) {
                const float* pr = &ps[(wn * 64 + nt * 8 + grp) * ROWP + k + qid];
                uint32_t b0 = __float_as_uint(pr[0]);
                uint32_t b1 = __float_as_uint(pr[4]);
                MMA_TF32(acc[0][nt], a[0], b0, b1);
                MMA_TF32(acc[1][nt], a[1], b0, b1);
            }
        }
        __syncthreads();
    }

    // epilogue: out = x + g * rinv_j * acc
    const float g = *gam;
    const float* xb = x + (size_t)b * NC * NL;
    float* ob = out + (size_t)b * NC * NL;
    float2 rv[8];
#pragma unroll
    for (int nt = 0; nt < 8; nt++)
        rv[nt] = *(const float2*)&g_rinv[b * NL + j0 + wn * 64 + nt * 8 + qid * 2];

#pragma unroll
    for (int mt = 0; mt < 2; mt++) {
        const int c = c0 + wm * 32 + mt * 16 + grp;
#pragma unroll
        for (int nt = 0; nt < 8; nt++) {
            const int j = j0 + wn * 64 + nt * 8 + qid * 2;
            {
                const size_t o = (size_t)c * NL + j;
                float2 xv = *(const float2*)(xb + o);
                float2 r = make_float2(xv.x + g * rv[nt].x * acc[mt][nt][0],
                                       xv.y + g * rv[nt].y * acc[mt][nt][1]);
                *(float2*)(ob + o) = r;
            }
            {
                const size_t o = (size_t)(c + 8) * NL + j;
                float2 xv = *(const float2*)(xb + o);
                float2 r = make_float2(xv.x + g * rv[nt].x * acc[mt][nt][2],
                                       xv.y + g * rv[nt].y * acc[mt][nt][3]);
                *(float2*)(ob + o) = r;
            }
        }
    }
}

// ---------------------------------------------------------------------------
extern "C" void kernel_launch(void* const* d_in, const int* in_sizes, int n_in,
                              void* d_out, int out_size) {
    (void)in_sizes; (void)n_in; (void)out_size;
    const float* x   = (const float*)d_in[0];
    const float* W1  = (const float*)d_in[1];
    const float* W2  = (const float*)d_in[2];
    const float* gam = (const float*)d_in[3];
    float* out = (float*)d_out;

    cudaFuncSetAttribute(k_scores_mma, cudaFuncAttributeMaxDynamicSharedMemorySize, SMEM_SC);
    cudaFuncSetAttribute(k_out_mma, cudaFuncAttributeMaxDynamicSharedMemorySize, SMEM_OUT);

    k_zero      <<<NB * NL / 1024, 1024>>>();
    k_proj      <<<dim3(NL / 64, NB), 256>>>(x, W1, W2);
    k_round     <<<(NB * NC * NL) / 1024, 256>>>(x);
    k_scores_mma<<<dim3(NL / 128, NL / 128, NB), 256, SMEM_SC>>>();
    k_rinv      <<<NB * NL / 1024, 1024>>>();
    k_out_mma   <<<dim3(NL / 128, NC / 128, NB), 256, SMEM_OUT>>>(x, gam, out);
}

// round 6
// speedup vs baseline: 2.7918x; 1.0008x over previous
#include <cuda_runtime.h>
#include <cuda_fp16.h>
#include <cstdint>

#define NB 8
#define NC 512
#define NL 2048
#define NT 64

// Scratch (static device globals — no allocation in kernel_launch)
__device__ float  g_Q[NB * NL * NT];             // [b][l][t]  4 MB
__device__ float  g_K[NB * NL * NT];             // [b][l][t]  4 MB
__device__ float  g_S[(size_t)NB * NL * NL];     // [b][j][i]  exp(scores) fp32  128 MB
__device__ __half g_Ph[(size_t)NB * NL * NL];    // [b][j][i]  normalized P fp16  64 MB
__device__ __half g_Xh[(size_t)NB * NC * NL];    // x in fp16                     16 MB
__device__ float  g_sum[NB * NL];
__device__ float  g_rinv[NB * NL];

__device__ __forceinline__ float to_tf32(float v) {
    uint32_t r;
    asm("cvt.rna.tf32.f32 %0, %1;" : "=r"(r) : "f"(v));
    return __uint_as_float(r);
}
__device__ __forceinline__ uint32_t smem_u32(const void* p) {
    uint32_t r;
    asm("{ .reg .u64 t; cvta.to.shared.u64 t, %1; cvt.u32.u64 %0, t; }" : "=r"(r) : "l"(p));
    return r;
}
__device__ __forceinline__ void cp16(uint32_t dst, const void* src) {
    asm volatile("cp.async.cg.shared.global [%0], [%1], 16;\n" :: "r"(dst), "l"(src));
}

#define MMA_TF32(ac, A, b0v, b1v)                                             \
    asm volatile("mma.sync.aligned.m16n8k8.row.col.f32.tf32.tf32.f32 "        \
                 "{%0,%1,%2,%3}, {%4,%5,%6,%7}, {%8,%9}, {%0,%1,%2,%3};"      \
                 : "+f"(ac[0]), "+f"(ac[1]), "+f"(ac[2]), "+f"(ac[3])         \
                 : "r"(A[0]), "r"(A[1]), "r"(A[2]), "r"(A[3]),                \
                   "r"(b0v), "r"(b1v));

#define MMA_F16(ac, A, b0v, b1v)                                              \
    asm volatile("mma.sync.aligned.m16n8k16.row.col.f32.f16.f16.f32 "         \
                 "{%0,%1,%2,%3}, {%4,%5,%6,%7}, {%8,%9}, {%0,%1,%2,%3};"      \
                 : "+f"(ac[0]), "+f"(ac[1]), "+f"(ac[2]), "+f"(ac[3])         \
                 : "r"(A[0]), "r"(A[1]), "r"(A[2]), "r"(A[3]),                \
                   "r"(b0v), "r"(b1v));

// ---------------------------------------------------------------------------
// Tiny kernels
// ---------------------------------------------------------------------------
__global__ void k_zero() { g_sum[blockIdx.x * 1024 + threadIdx.x] = 0.f; }
__global__ void k_rinv() {
    const int i = blockIdx.x * 1024 + threadIdx.x;
    g_rinv[i] = 1.0f / g_sum[i];
}

// x -> fp16
__global__ __launch_bounds__(256) void k_half(const float* __restrict__ x) {
    const size_t e = ((size_t)blockIdx.x * 256 + threadIdx.x) * 8;
    float4 v0 = *(const float4*)(x + e);
    float4 v1 = *(const float4*)(x + e + 4);
    __half2 h[4];
    h[0] = __floats2half2_rn(v0.x, v0.y);
    h[1] = __floats2half2_rn(v0.z, v0.w);
    h[2] = __floats2half2_rn(v1.x, v1.y);
    h[3] = __floats2half2_rn(v1.z, v1.w);
    *(uint4*)(g_Xh + e) = *(const uint4*)h;
}

// P fp32 unnormalized -> fp16 normalized (one block per row)
__global__ __launch_bounds__(256) void k_norm() {
    const int row = blockIdx.x;                    // [0, NB*NL)
    const float rinv = g_rinv[row];
    const float* src = g_S + (size_t)row * NL;
    __half* dst = g_Ph + (size_t)row * NL;
    const int i = threadIdx.x * 8;
    float4 v0 = *(const float4*)(src + i);
    float4 v1 = *(const float4*)(src + i + 4);
    __half2 h[4];
    h[0] = __floats2half2_rn(v0.x * rinv, v0.y * rinv);
    h[1] = __floats2half2_rn(v0.z * rinv, v0.w * rinv);
    h[2] = __floats2half2_rn(v1.x * rinv, v1.y * rinv);
    h[3] = __floats2half2_rn(v1.z * rinv, v1.w * rinv);
    *(uint4*)(dst + i) = *(const uint4*)h;
}

// ---------------------------------------------------------------------------
// Kernel 1: Q/K projection -> [b][l][t] layout (t contiguous).
// ---------------------------------------------------------------------------
__global__ __launch_bounds__(256) void k_proj(const float* __restrict__ x,
                                              const float* __restrict__ W1,
                                              const float* __restrict__ W2) {
    __shared__ float xs[32][68];
    __shared__ float w1s[64][33];
    __shared__ float w2s[64][33];
    const int b = blockIdx.y;
    const int l0 = blockIdx.x * 64;
    const int tid = threadIdx.x;
    const int tx = tid & 15, ty = tid >> 4;
    float qa[4][4] = {}, ka[4][4] = {};
    const float* xb = x + (size_t)b * NC * NL;

    for (int c0 = 0; c0 < NC; c0 += 32) {
#pragma unroll
        for (int u = 0; u < 8; u++) {
            int e = tid + u * 256;
            int cc = e >> 6, ll = e & 63;
            xs[cc][ll] = xb[(size_t)(c0 + cc) * NL + l0 + ll];
        }
#pragma unroll
        for (int u = 0; u < 8; u++) {
            int e = tid + u * 256;
            int t = e >> 5, cc = e & 31;
            w1s[t][cc] = W1[t * NC + c0 + cc];
            w2s[t][cc] = W2[t * NC + c0 + cc];
        }
        __syncthreads();
#pragma unroll
        for (int kc = 0; kc < 32; kc++) {
            float4 xv = *(const float4*)&xs[kc][tx * 4];
            float lv[4] = {xv.x, xv.y, xv.z, xv.w};
#pragma unroll
            for (int tt = 0; tt < 4; tt++) {
                float wq = w1s[ty * 4 + tt][kc];
                float wk = w2s[ty * 4 + tt][kc];
#pragma unroll
                for (int ll = 0; ll < 4; ll++) {
                    qa[tt][ll] += wq * lv[ll];
                    ka[tt][ll] += wk * lv[ll];
                }
            }
        }
        __syncthreads();
    }
#pragma unroll
    for (int ll = 0; ll < 4; ll++) {
        const int l = l0 + tx * 4 + ll;
        float4 q4 = make_float4(qa[0][ll], qa[1][ll], qa[2][ll], qa[3][ll]);
        float4 k4 = make_float4(ka[0][ll], ka[1][ll], ka[2][ll], ka[3][ll]);
        *(float4*)&g_Q[((size_t)b * NL + l) * NT + ty * 4] = q4;
        *(float4*)&g_K[((size_t)b * NL + l) * NT + ty * 4] = k4;
    }
}

// ---------------------------------------------------------------------------
// Kernel 2 (mma tf32, hi/lo split): g_S[b][j][i] = exp(Q[j]·K[i]) fp32,
// row sums -> atomicAdd g_sum. No max subtraction (scores bounded).
// ---------------------------------------------------------------------------
#define SROWP 68
#define STILE_F (128 * SROWP)
#define SMEM_SC (2 * STILE_F * 4)   // 69632 B

__global__ __launch_bounds__(256) void k_scores_mma() {
    extern __shared__ float sm[];
    const uint32_t sb = smem_u32(sm);
    const int tid = threadIdx.x;
    const int b = blockIdx.z;
    const int j0 = blockIdx.y * 128;
    const int i0 = blockIdx.x * 128;
    const float* Qb = g_Q + (size_t)b * NL * NT;
    const float* Kb = g_K + (size_t)b * NL * NT;

#pragma unroll
    for (int u = 0; u < 8; u++) {
        int e = tid + u * 256;
        int r = e >> 4, seg = e & 15;
        cp16(sb + (r * SROWP + seg * 4) * 4, Qb + (size_t)(j0 + r) * NT + seg * 4);
        cp16(sb + (STILE_F + r * SROWP + seg * 4) * 4, Kb + (size_t)(i0 + r) * NT + seg * 4);
    }
    asm volatile("cp.async.commit_group;\n" ::: "memory");
    asm volatile("cp.async.wait_group 0;\n" ::: "memory");
    __syncthreads();

    const float* qs = sm;
    const float* ks = sm + STILE_F;
    const int wid = tid >> 5, lane = tid & 31;
    const int wm = wid & 3;
    const int wn = wid >> 2;
    const int grp = lane >> 2, qid = lane & 3;

    float acc[2][8][4];
#pragma unroll
    for (int mt = 0; mt < 2; mt++)
#pragma unroll
        for (int nt = 0; nt < 8; nt++)
#pragma unroll
            for (int q = 0; q < 4; q++) acc[mt][nt][q] = 0.f;

#pragma unroll
    for (int ks8 = 0; ks8 < 8; ks8++) {
        const int k = ks8 * 8;
        uint32_t ahi[2][4], alo[2][4];
#pragma unroll
        for (int mt = 0; mt < 2; mt++) {
            const float* r0 = &qs[(wm * 32 + mt * 16 + grp) * SROWP + k + qid];
            const float* r8 = r0 + 8 * SROWP;
            float v[4] = {r0[0], r8[0], r0[4], r8[4]};
#pragma unroll
            for (int q = 0; q < 4; q++) {
                float hi = to_tf32(v[q]);
                ahi[mt][q] = __float_as_uint(hi);
                alo[mt][q] = __float_as_uint(to_tf32(v[q] - hi));
            }
        }
        uint32_t bhi[8][2], blo[8][2];
#pragma unroll
        for (int nt = 0; nt < 8; nt++) {
            const float* pr = &ks[(wn * 64 + nt * 8 + grp) * SROWP + k + qid];
            float v0 = pr[0], v1 = pr[4];
            float h0 = to_tf32(v0), h1 = to_tf32(v1);
            bhi[nt][0] = __float_as_uint(h0);
            bhi[nt][1] = __float_as_uint(h1);
            blo[nt][0] = __float_as_uint(to_tf32(v0 - h0));
            blo[nt][1] = __float_as_uint(to_tf32(v1 - h1));
        }
#pragma unroll
        for (int nt = 0; nt < 8; nt++)
#pragma unroll
            for (int mt = 0; mt < 2; mt++) {
                MMA_TF32(acc[mt][nt], ahi[mt], bhi[nt][0], bhi[nt][1]);
                MMA_TF32(acc[mt][nt], ahi[mt], blo[nt][0], blo[nt][1]);
                MMA_TF32(acc[mt][nt], alo[mt], bhi[nt][0], bhi[nt][1]);
            }
    }

    float* Pb = g_S + (size_t)b * NL * NL;
    float rsum[2][2] = {};
#pragma unroll
    for (int mt = 0; mt < 2; mt++) {
        const int r0 = j0 + wm * 32 + mt * 16 + grp;
#pragma unroll
        for (int nt = 0; nt < 8; nt++) {
            const int col = i0 + wn * 64 + nt * 8 + qid * 2;
            float e0 = __expf(acc[mt][nt][0]);
            float e1 = __expf(acc[mt][nt][1]);
            float e2 = __expf(acc[mt][nt][2]);
            float e3 = __expf(acc[mt][nt][3]);
            rsum[mt][0] += e0 + e1;
            rsum[mt][1] += e2 + e3;
            *(float2*)&Pb[(size_t)r0 * NL + col] = make_float2(e0, e1);
            *(float2*)&Pb[(size_t)(r0 + 8) * NL + col] = make_float2(e2, e3);
        }
    }
#pragma unroll
    for (int mt = 0; mt < 2; mt++)
#pragma unroll
        for (int h = 0; h < 2; h++) {
            float v = rsum[mt][h];
            v += __shfl_xor_sync(0xffffffffu, v, 1);
            v += __shfl_xor_sync(0xffffffffu, v, 2);
            if (qid == 0)
                atomicAdd(&g_sum[b * NL + j0 + wm * 32 + mt * 16 + grp + h * 8], v);
        }
}

// ---------------------------------------------------------------------------
// Kernel 4 (mma fp16): out[b][c][j] = x[b][c][j] + g * sum_i Ph[j][i]*Xh[c][i]
// CTA 128(c) x 128(j), 8 warps (4m x 2n), warp tile 32x64, K chunks of 32.
// Rows padded to 40 halves -> conflict-free 32-bit frag loads.
// ---------------------------------------------------------------------------
#define ICH 32
#define NCHK (NL / ICH)             // 64
#define ROWH 40
#define HTILE (128 * ROWH)          // halves per tile
#define HSTG (2 * HTILE)            // halves per stage (A + B)
#define SMEM_OUT (2 * HSTG * 2)     // bytes = 40960

__global__ __launch_bounds__(256, 2) void k_out_h(const float* __restrict__ x,
                                                  const float* __restrict__ gam,
                                                  float* __restrict__ out) {
    extern __shared__ __half smh[];
    const uint32_t sb = smem_u32(smh);
    const int tid = threadIdx.x;
    const int b = blockIdx.z;
    const int c0 = blockIdx.y * 128;
    const int j0 = blockIdx.x * 128;
    const __half* xhb = g_Xh + (size_t)b * NC * NL;
    const __half* phb = g_Ph + (size_t)b * NL * NL;

    auto load_chunk = [&](int n, int stg) {
        const int i0 = n * ICH;
        const uint32_t xbase = sb + (uint32_t)(stg * HSTG) * 2;
        const uint32_t pbase = xbase + HTILE * 2;
#pragma unroll
        for (int u = 0; u < 2; u++) {
            int e = tid + u * 256;
            int r = e & 127, seg = e >> 7;   // consecutive threads -> distinct rows
            cp16(xbase + (r * ROWH + seg * 8) * 2, xhb + (size_t)(c0 + r) * NL + i0 + seg * 8);
        }
#pragma unroll
        for (int u = 0; u < 2; u++) {
            int e = tid + u * 256;
            int r = e & 127, seg = e >> 7;
            cp16(pbase + (r * ROWH + seg * 8) * 2, phb + (size_t)(j0 + r) * NL + i0 + seg * 8);
        }
        asm volatile("cp.async.commit_group;\n" ::: "memory");
    };

    const int wid = tid >> 5, lane = tid & 31;
    const int wm = wid & 3;        // c block
    const int wn = wid >> 2;       // j block
    const int grp = lane >> 2, qid = lane & 3;

    float acc[2][8][4];
#pragma unroll
    for (int mt = 0; mt < 2; mt++)
#pragma unroll
        for (int nt = 0; nt < 8; nt++)
#pragma unroll
            for (int q = 0; q < 4; q++) acc[mt][nt][q] = 0.f;

    load_chunk(0, 0);

    for (int n = 0; n < NCHK; n++) {
        const int s = n & 1;
        if (n + 1 < NCHK) {
            load_chunk(n + 1, 1 - s);
            asm volatile("cp.async.wait_group 1;\n" ::: "memory");
        } else {
            asm volatile("cp.async.wait_group 0;\n" ::: "memory");
        }
        __syncthreads();

        const __half* xs = smh + s * HSTG;
        const __half* ps = xs + HTILE;
#pragma unroll
        for (int kh = 0; kh < 2; kh++) {       // two k16 sub-chunks
            const int k = kh * 16;
            uint32_t a[2][4];
#pragma unroll
            for (int mt = 0; mt < 2; mt++) {
                const __half* r0 = &xs[(wm * 32 + mt * 16 + grp) * ROWH + k + 2 * qid];
                const __half* r8 = r0 + 8 * ROWH;
                a[mt][0] = *(const uint32_t*)r0;
                a[mt][1] = *(const uint32_t*)r8;
                a[mt][2] = *(const uint32_t*)(r0 + 8);
                a[mt][3] = *(const uint32_t*)(r8 + 8);
            }
#pragma unroll
            for (int nt = 0; nt < 8; nt++) {
                const __half* pr = &ps[(wn * 64 + nt * 8 + grp) * ROWH + k + 2 * qid];
                uint32_t b0 = *(const uint32_t*)pr;
                uint32_t b1 = *(const uint32_t*)(pr + 8);
                MMA_F16(acc[0][nt], a[0], b0, b1);
                MMA_F16(acc[1][nt], a[1], b0, b1);
            }
        }
        __syncthreads();
    }

    // epilogue: out = x + g * acc   (P already normalized)
    const float g = *gam;
    const float* xb = x + (size_t)b * NC * NL;
    float* ob = out + (size_t)b * NC * NL;
#pragma unroll
    for (int mt = 0; mt < 2; mt++) {
        const int c = c0 + wm * 32 + mt * 16 + grp;
#pragma unroll
        for (int nt = 0; nt < 8; nt++) {
            const int j = j0 + wn * 64 + nt * 8 + qid * 2;
            {
                const size_t o = (size_t)c * NL + j;
                float2 xv = *(const float2*)(xb + o);
                float2 r = make_float2(xv.x + g * acc[mt][nt][0],
                                       xv.y + g * acc[mt][nt][1]);
                *(float2*)(ob + o) = r;
            }
            {
                const size_t o = (size_t)(c + 8) * NL + j;
                float2 xv = *(const float2*)(xb + o);
                float2 r = make_float2(xv.x + g * acc[mt][nt][2],
                                       xv.y + g * acc[mt][nt][3]);
                *(float2*)(ob + o) = r;
            }
        }
    }
}

// ---------------------------------------------------------------------------
extern "C" void kernel_launch(void* const* d_in, const int* in_sizes, int n_in,
                              void* d_out, int out_size) {
    (void)in_sizes; (void)n_in; (void)out_size;
    const float* x   = (const float*)d_in[0];
    const float* W1  = (const float*)d_in[1];
    const float* W2  = (const float*)d_in[2];
    const float* gam = (const float*)d_in[3];
    float* out = (float*)d_out;

    cudaFuncSetAttribute(k_scores_mma, cudaFuncAttributeMaxDynamicSharedMemorySize, SMEM_SC);
    cudaFuncSetAttribute(k_out_h, cudaFuncAttributeMaxDynamicSharedMemorySize, SMEM_OUT);

    k_zero      <<<NB * NL / 1024, 1024>>>();
    k_proj      <<<dim3(NL / 64, NB), 256>>>(x, W1, W2);
    k_half      <<<(NB * NC * NL) / (256 * 8), 256>>>(x);
    k_scores_mma<<<dim3(NL / 128, NL / 128, NB), 256, SMEM_SC>>>();
    k_rinv      <<<NB * NL / 1024, 1024>>>();
    k_norm      <<<NB * NL, 256>>>();
    k_out_h     <<<dim3(NL / 128, NC / 128, NB), 256, SMEM_OUT>>>(x, gam, out);
}

// round 7
// speedup vs baseline: 4.0655x; 1.4562x over previous
#include <cuda_runtime.h>
#include <cuda_fp16.h>
#include <cstdint>

#define NB 8
#define NC 512
#define NL 2048
#define NT 64

// Scratch (static device globals — no allocation in kernel_launch)
__device__ __half g_Qh[NB * NL * NT];            // [b][l][t] hi  2 MB
__device__ __half g_Ql[NB * NL * NT];            // [b][l][t] lo  2 MB
__device__ __half g_Kh[NB * NL * NT];
__device__ __half g_Kl[NB * NL * NT];
__device__ float  g_S[(size_t)NB * NL * NL];     // exp(scores) fp32   128 MB
__device__ __half g_Ph[(size_t)NB * NL * NL];    // normalized P fp16   64 MB
__device__ __half g_Xh[(size_t)NB * NC * NL];    // x fp16              16 MB
__device__ float  g_sum[NB * NL];
__device__ float  g_rinv[NB * NL];

__device__ __forceinline__ uint32_t smem_u32(const void* p) {
    uint32_t r;
    asm("{ .reg .u64 t; cvta.to.shared.u64 t, %1; cvt.u32.u64 %0, t; }" : "=r"(r) : "l"(p));
    return r;
}
__device__ __forceinline__ void cp16(uint32_t dst, const void* src) {
    asm volatile("cp.async.cg.shared.global [%0], [%1], 16;\n" :: "r"(dst), "l"(src));
}
__device__ __forceinline__ void ldm4(uint32_t* r, uint32_t addr) {
    asm volatile("ldmatrix.sync.aligned.m8n8.x4.shared.b16 {%0,%1,%2,%3}, [%4];"
                 : "=r"(r[0]), "=r"(r[1]), "=r"(r[2]), "=r"(r[3]) : "r"(addr));
}

#define MMA_F16(ac, A, b0v, b1v)                                              \
    asm volatile("mma.sync.aligned.m16n8k16.row.col.f32.f16.f16.f32 "         \
                 "{%0,%1,%2,%3}, {%4,%5,%6,%7}, {%8,%9}, {%0,%1,%2,%3};"      \
                 : "+f"(ac[0]), "+f"(ac[1]), "+f"(ac[2]), "+f"(ac[3])         \
                 : "r"(A[0]), "r"(A[1]), "r"(A[2]), "r"(A[3]),                \
                   "r"(b0v), "r"(b1v));

// ---------------------------------------------------------------------------
// Tiny kernels
// ---------------------------------------------------------------------------
__global__ void k_zero() { g_sum[blockIdx.x * 1024 + threadIdx.x] = 0.f; }
__global__ void k_rinv() {
    const int i = blockIdx.x * 1024 + threadIdx.x;
    g_rinv[i] = 1.0f / g_sum[i];
}

// x -> fp16
__global__ __launch_bounds__(256) void k_half(const float* __restrict__ x) {
    const size_t e = ((size_t)blockIdx.x * 256 + threadIdx.x) * 8;
    float4 v0 = *(const float4*)(x + e);
    float4 v1 = *(const float4*)(x + e + 4);
    __half2 h[4];
    h[0] = __floats2half2_rn(v0.x, v0.y);
    h[1] = __floats2half2_rn(v0.z, v0.w);
    h[2] = __floats2half2_rn(v1.x, v1.y);
    h[3] = __floats2half2_rn(v1.z, v1.w);
    *(uint4*)(g_Xh + e) = *(const uint4*)h;
}

// P fp32 unnormalized -> fp16 normalized (one block per row)
__global__ __launch_bounds__(256) void k_norm() {
    const int row = blockIdx.x;
    const float rinv = g_rinv[row];
    const float* src = g_S + (size_t)row * NL;
    __half* dst = g_Ph + (size_t)row * NL;
    const int i = threadIdx.x * 8;
    float4 v0 = *(const float4*)(src + i);
    float4 v1 = *(const float4*)(src + i + 4);
    __half2 h[4];
    h[0] = __floats2half2_rn(v0.x * rinv, v0.y * rinv);
    h[1] = __floats2half2_rn(v0.z * rinv, v0.w * rinv);
    h[2] = __floats2half2_rn(v1.x * rinv, v1.y * rinv);
    h[3] = __floats2half2_rn(v1.z * rinv, v1.w * rinv);
    *(uint4*)(dst + i) = *(const uint4*)h;
}

// ---------------------------------------------------------------------------
// Kernel 1: Q/K projection -> fp16 hi/lo, [b][l][t] layout.
// ---------------------------------------------------------------------------
__global__ __launch_bounds__(256) void k_proj(const float* __restrict__ x,
                                              const float* __restrict__ W1,
                                              const float* __restrict__ W2) {
    __shared__ float xs[32][68];
    __shared__ float w1s[64][33];
    __shared__ float w2s[64][33];
    const int b = blockIdx.y;
    const int l0 = blockIdx.x * 64;
    const int tid = threadIdx.x;
    const int tx = tid & 15, ty = tid >> 4;
    float qa[4][4] = {}, ka[4][4] = {};
    const float* xb = x + (size_t)b * NC * NL;

    for (int c0 = 0; c0 < NC; c0 += 32) {
#pragma unroll
        for (int u = 0; u < 8; u++) {
            int e = tid + u * 256;
            int cc = e >> 6, ll = e & 63;
            xs[cc][ll] = xb[(size_t)(c0 + cc) * NL + l0 + ll];
        }
#pragma unroll
        for (int u = 0; u < 8; u++) {
            int e = tid + u * 256;
            int t = e >> 5, cc = e & 31;
            w1s[t][cc] = W1[t * NC + c0 + cc];
            w2s[t][cc] = W2[t * NC + c0 + cc];
        }
        __syncthreads();
#pragma unroll
        for (int kc = 0; kc < 32; kc++) {
            float4 xv = *(const float4*)&xs[kc][tx * 4];
            float lv[4] = {xv.x, xv.y, xv.z, xv.w};
#pragma unroll
            for (int tt = 0; tt < 4; tt++) {
                float wq = w1s[ty * 4 + tt][kc];
                float wk = w2s[ty * 4 + tt][kc];
#pragma unroll
                for (int ll = 0; ll < 4; ll++) {
                    qa[tt][ll] += wq * lv[ll];
                    ka[tt][ll] += wk * lv[ll];
                }
            }
        }
        __syncthreads();
    }
#pragma unroll
    for (int ll = 0; ll < 4; ll++) {
        const int l = l0 + tx * 4 + ll;
        const size_t off = ((size_t)b * NL + l) * NT + ty * 4;
        __half qh[4], ql[4], kh[4], kl[4];
#pragma unroll
        for (int tt = 0; tt < 4; tt++) {
            float qv = qa[tt][ll], kv = ka[tt][ll];
            __half h1 = __float2half_rn(qv);
            __half h2 = __float2half_rn(kv);
            qh[tt] = h1; ql[tt] = __float2half_rn(qv - __half2float(h1));
            kh[tt] = h2; kl[tt] = __float2half_rn(kv - __half2float(h2));
        }
        *(uint2*)&g_Qh[off] = *(uint2*)qh;
        *(uint2*)&g_Ql[off] = *(uint2*)ql;
        *(uint2*)&g_Kh[off] = *(uint2*)kh;
        *(uint2*)&g_Kl[off] = *(uint2*)kl;
    }
}

// ---------------------------------------------------------------------------
// Kernel 2 (fp16 hi/lo 3-term mma): g_S[b][j][i] = exp(Q[j]·K[i]) fp32,
// row sums -> atomicAdd g_sum. CTA 128j x 128i, 8 warps (4m x 2n).
// ---------------------------------------------------------------------------
#define SROWH 72
#define STILE_H (128 * SROWH)
#define SMEM_SC (4 * STILE_H * 2)   // 73728 B  (Qh, Ql, Kh, Kl tiles)

__global__ __launch_bounds__(256) void k_scores_mma() {
    extern __shared__ char smraw[];
    __half* smh = (__half*)smraw;
    const uint32_t sb = smem_u32(smraw);
    const int tid = threadIdx.x;
    const int b = blockIdx.z;
    const int j0 = blockIdx.y * 128;
    const int i0 = blockIdx.x * 128;

    const __half* srcs[4] = {g_Qh + ((size_t)b * NL + j0) * NT,
                             g_Ql + ((size_t)b * NL + j0) * NT,
                             g_Kh + ((size_t)b * NL + i0) * NT,
                             g_Kl + ((size_t)b * NL + i0) * NT};
#pragma unroll
    for (int t = 0; t < 4; t++) {
#pragma unroll
        for (int u = 0; u < 4; u++) {
            int e = tid + u * 256;          // [0,1024): r*8+seg
            int r = e >> 3, seg = e & 7;
            cp16(sb + (t * STILE_H + r * SROWH + seg * 8) * 2,
                 srcs[t] + (size_t)r * NT + seg * 8);
        }
    }
    asm volatile("cp.async.commit_group;\n" ::: "memory");
    asm volatile("cp.async.wait_group 0;\n" ::: "memory");
    __syncthreads();

    const int wid = tid >> 5, lane = tid & 31;
    const int wm = wid & 3;            // j block: wm*32
    const int wn = wid >> 2;           // i block: wn*64
    const int grp = lane >> 2, qid = lane & 3;
    // ldmatrix per-lane address components
    const int rowA = (lane & 7) + ((lane >> 3) & 1) * 8;
    const int colA = (lane >> 4) * 8;
    const int rowB = (lane & 7) + (lane >> 4) * 8;
    const int colB = ((lane >> 3) & 1) * 8;

    const uint32_t qh_b = sb;
    const uint32_t ql_b = sb + STILE_H * 2;
    const uint32_t kh_b = sb + 2 * STILE_H * 2;
    const uint32_t kl_b = sb + 3 * STILE_H * 2;

    float acc[2][8][4];
#pragma unroll
    for (int mt = 0; mt < 2; mt++)
#pragma unroll
        for (int nt = 0; nt < 8; nt++)
#pragma unroll
            for (int q = 0; q < 4; q++) acc[mt][nt][q] = 0.f;

#pragma unroll
    for (int kh16 = 0; kh16 < 4; kh16++) {
        const int k = kh16 * 16;
        uint32_t ah[2][4], al[2][4];
#pragma unroll
        for (int mt = 0; mt < 2; mt++) {
            const uint32_t ao = ((wm * 32 + mt * 16 + rowA) * SROWH + k + colA) * 2;
            ldm4(ah[mt], qh_b + ao);
            ldm4(al[mt], ql_b + ao);
        }
#pragma unroll
        for (int p = 0; p < 4; p++) {
            const uint32_t bo = ((wn * 64 + p * 16 + rowB) * SROWH + k + colB) * 2;
            uint32_t bh[4], bl[4];
            ldm4(bh, kh_b + bo);
            ldm4(bl, kl_b + bo);
#pragma unroll
            for (int e = 0; e < 2; e++) {
                const int nt = p * 2 + e;
#pragma unroll
                for (int mt = 0; mt < 2; mt++) {
                    MMA_F16(acc[mt][nt], ah[mt], bh[2 * e], bh[2 * e + 1]);
                    MMA_F16(acc[mt][nt], ah[mt], bl[2 * e], bl[2 * e + 1]);
                    MMA_F16(acc[mt][nt], al[mt], bh[2 * e], bh[2 * e + 1]);
                }
            }
        }
    }

    // epilogue: exp (no max subtraction), store fp32, row sums via atomics
    float* Pb = g_S + (size_t)b * NL * NL;
    float rsum[2][2] = {};
#pragma unroll
    for (int mt = 0; mt < 2; mt++) {
        const int r0 = j0 + wm * 32 + mt * 16 + grp;
#pragma unroll
        for (int nt = 0; nt < 8; nt++) {
            const int col = i0 + wn * 64 + nt * 8 + qid * 2;
            float e0 = __expf(acc[mt][nt][0]);
            float e1 = __expf(acc[mt][nt][1]);
            float e2 = __expf(acc[mt][nt][2]);
            float e3 = __expf(acc[mt][nt][3]);
            rsum[mt][0] += e0 + e1;
            rsum[mt][1] += e2 + e3;
            *(float2*)&Pb[(size_t)r0 * NL + col] = make_float2(e0, e1);
            *(float2*)&Pb[(size_t)(r0 + 8) * NL + col] = make_float2(e2, e3);
        }
    }
#pragma unroll
    for (int mt = 0; mt < 2; mt++)
#pragma unroll
        for (int h = 0; h < 2; h++) {
            float v = rsum[mt][h];
            v += __shfl_xor_sync(0xffffffffu, v, 1);
            v += __shfl_xor_sync(0xffffffffu, v, 2);
            if (qid == 0)
                atomicAdd(&g_sum[b * NL + j0 + wm * 32 + mt * 16 + grp + h * 8], v);
        }
}

// ---------------------------------------------------------------------------
// Kernel 4 (fp16 mma, 4-stage pipeline, ldmatrix):
// out[b][c][j] = x[b][c][j] + g * sum_i Ph[j][i] * Xh[c][i]
// CTA 128(c) x 128(j), 8 warps (4m x 2n), K chunks of 32.
// ---------------------------------------------------------------------------
#define ICH 32
#define NCHK (NL / ICH)             // 64
#define NSTG 4
#define ROWH 40
#define HTILE (128 * ROWH)          // halves per tile
#define HSTG (2 * HTILE)            // halves per stage (X + P)
#define SMEM_OUT (NSTG * HSTG * 2)  // 81920 B

__global__ __launch_bounds__(256, 2) void k_out_h(const float* __restrict__ x,
                                                  const float* __restrict__ gam,
                                                  float* __restrict__ out) {
    extern __shared__ char smraw[];
    const uint32_t sb = smem_u32(smraw);
    const int tid = threadIdx.x;
    const int b = blockIdx.z;
    const int c0 = blockIdx.y * 128;
    const int j0 = blockIdx.x * 128;
    const __half* xhb = g_Xh + (size_t)b * NC * NL;
    const __half* phb = g_Ph + (size_t)b * NL * NL;

    auto load_chunk = [&](int n) {
        const int stg = n % NSTG;
        const int i0 = n * ICH;
        const uint32_t xbase = sb + (uint32_t)(stg * HSTG) * 2;
        const uint32_t pbase = xbase + HTILE * 2;
#pragma unroll
        for (int u = 0; u < 2; u++) {
            int e = tid + u * 256;        // [0,512): r = e>>2, seg = e&3
            int r = e >> 2, seg = e & 3;
            cp16(xbase + (r * ROWH + seg * 8) * 2, xhb + (size_t)(c0 + r) * NL + i0 + seg * 8);
        }
#pragma unroll
        for (int u = 0; u < 2; u++) {
            int e = tid + u * 256;
            int r = e >> 2, seg = e & 3;
            cp16(pbase + (r * ROWH + seg * 8) * 2, phb + (size_t)(j0 + r) * NL + i0 + seg * 8);
        }
        asm volatile("cp.async.commit_group;\n" ::: "memory");
    };

    const int wid = tid >> 5, lane = tid & 31;
    const int wm = wid & 3;        // c block
    const int wn = wid >> 2;       // j block
    const int grp = lane >> 2, qid = lane & 3;
    const int rowA = (lane & 7) + ((lane >> 3) & 1) * 8;
    const int colA = (lane >> 4) * 8;
    const int rowB = (lane & 7) + (lane >> 4) * 8;
    const int colB = ((lane >> 3) & 1) * 8;

    float acc[2][8][4];
#pragma unroll
    for (int mt = 0; mt < 2; mt++)
#pragma unroll
        for (int nt = 0; nt < 8; nt++)
#pragma unroll
            for (int q = 0; q < 4; q++) acc[mt][nt][q] = 0.f;

    load_chunk(0);
    load_chunk(1);
    load_chunk(2);

    for (int n = 0; n < NCHK; n++) {
        asm volatile("cp.async.wait_group 2;\n" ::: "memory");
        __syncthreads();

        const int stg = n % NSTG;
        const uint32_t xsb = sb + (uint32_t)(stg * HSTG) * 2;
        const uint32_t psb = xsb + HTILE * 2;
#pragma unroll
        for (int kh16 = 0; kh16 < 2; kh16++) {
            const int k = kh16 * 16;
            uint32_t a[2][4];
#pragma unroll
            for (int mt = 0; mt < 2; mt++)
                ldm4(a[mt], xsb + ((wm * 32 + mt * 16 + rowA) * ROWH + k + colA) * 2);
#pragma unroll
            for (int p = 0; p < 4; p++) {
                uint32_t b4[4];
                ldm4(b4, psb + ((wn * 64 + p * 16 + rowB) * ROWH + k + colB) * 2);
                MMA_F16(acc[0][2 * p], a[0], b4[0], b4[1]);
                MMA_F16(acc[1][2 * p], a[1], b4[0], b4[1]);
                MMA_F16(acc[0][2 * p + 1], a[0], b4[2], b4[3]);
                MMA_F16(acc[1][2 * p + 1], a[1], b4[2], b4[3]);
            }
        }

        if (n + 3 < NCHK) load_chunk(n + 3);
        else asm volatile("cp.async.commit_group;\n" ::: "memory");
    }

    // epilogue: out = x + g * acc   (P already normalized)
    const float g = *gam;
    const float* xb = x + (size_t)b * NC * NL;
    float* ob = out + (size_t)b * NC * NL;
#pragma unroll
    for (int mt = 0; mt < 2; mt++) {
        const int c = c0 + wm * 32 + mt * 16 + grp;
#pragma unroll
        for (int nt = 0; nt < 8; nt++) {
            const int j = j0 + wn * 64 + nt * 8 + qid * 2;
            {
                const size_t o = (size_t)c * NL + j;
                float2 xv = *(const float2*)(xb + o);
                float2 r = make_float2(xv.x + g * acc[mt][nt][0],
                                       xv.y + g * acc[mt][nt][1]);
                *(float2*)(ob + o) = r;
            }
            {
                const size_t o = (size_t)(c + 8) * NL + j;
                float2 xv = *(const float2*)(xb + o);
                float2 r = make_float2(xv.x + g * acc[mt][nt][2],
                                       xv.y + g * acc[mt][nt][3]);
                *(float2*)(ob + o) = r;
            }
        }
    }
}

// ---------------------------------------------------------------------------
extern "C" void kernel_launch(void* const* d_in, const int* in_sizes, int n_in,
                              void* d_out, int out_size) {
    (void)in_sizes; (void)n_in; (void)out_size;
    const float* x   = (const float*)d_in[0];
    const float* W1  = (const float*)d_in[1];
    const float* W2  = (const float*)d_in[2];
    const float* gam = (const float*)d_in[3];
    float* out = (float*)d_out;

    cudaFuncSetAttribute(k_scores_mma, cudaFuncAttributeMaxDynamicSharedMemorySize, SMEM_SC);
    cudaFuncSetAttribute(k_out_h, cudaFuncAttributeMaxDynamicSharedMemorySize, SMEM_OUT);

    k_zero      <<<NB * NL / 1024, 1024>>>();
    k_proj      <<<dim3(NL / 64, NB), 256>>>(x, W1, W2);
    k_half      <<<(NB * NC * NL) / (256 * 8), 256>>>(x);
    k_scores_mma<<<dim3(NL / 128, NL / 128, NB), 256, SMEM_SC>>>();
    k_rinv      <<<NB * NL / 1024, 1024>>>();
    k_norm      <<<NB * NL, 256>>>();
    k_out_h     <<<dim3(NL / 128, NC / 128, NB), 256, SMEM_OUT>>>(x, gam, out);
}